// round 16
// baseline (speedup 1.0000x reference)
#include <cuda_runtime.h>
#include <cuda_bf16.h>

#define HGT 512
#define WID 512
#define BX  32
#define BY  4
#define RPT 16                   // rows (pixels) per thread
#define NT  (BX*BY)              // 128 threads
#define TILE_W (BX + 2)          // 34
#define TILE_H (BY*RPT + 2)      // 66

// compare-exchange: a<-min, b<-max  (2x FMNMX, alu pipe)
#define CE(a,b) { float lo_ = fminf(a,b); float hi_ = fmaxf(a,b); a = lo_; b = hi_; }

__global__ __launch_bounds__(NT, 12) void morph2d_kernel(
    const float* __restrict__ x,
    const float* __restrict__ se,
    const float* __restrict__ rnk,
    float* __restrict__ out)
{
    __shared__ float tile[TILE_H][TILE_W];
    __shared__ float s_w[9];     // exp(rank) numerators
    __shared__ float s_se[9];

    const int tx  = threadIdx.x;
    const int ty  = threadIdx.y;
    const int tid = ty * BX + tx;
    const int bb  = blockIdx.z;
    const int x0  = blockIdx.x * BX;
    const int y0  = blockIdx.y * (BY * RPT);

    const float* img = x + (size_t)bb * (HGT * WID);

    if (tid < 9) {
        s_w[tid]  = __expf(rnk[tid]);
        s_se[tid] = se[tid];
    }

    // cooperative halo tile load (zero-padded SAME); interior blocks unpredicated
    const bool interior = (x0 > 0) && (x0 + BX < WID) && (y0 > 0) && (y0 + BY * RPT < HGT);
    if (interior) {
        #pragma unroll
        for (int i = tid; i < TILE_H * TILE_W; i += NT) {
            int r = i / TILE_W;
            int c = i - r * TILE_W;
            tile[r][c] = __ldg(&img[(y0 + r - 1) * WID + (x0 + c - 1)]);
        }
    } else {
        #pragma unroll
        for (int i = tid; i < TILE_H * TILE_W; i += NT) {
            int r  = i / TILE_W;
            int c  = i - r * TILE_W;
            int gy = y0 + r - 1;
            int gx = x0 + c - 1;
            float v = 0.0f;
            if ((unsigned)gy < HGT && (unsigned)gx < WID)
                v = __ldg(&img[gy * WID + gx]);
            tile[r][c] = v;
        }
    }
    __syncthreads();

    // normalized softmax weights with final sort layer folded analytically:
    //   Wi*min + Wj*max = A*(a+b) + B*|a-b|,  A=(Wi+Wj)/2, B=(Wj-Wi)/2
    float W0 = s_w[0], W1 = s_w[1], W2 = s_w[2];
    float W3 = s_w[3], W4 = s_w[4], W5 = s_w[5];
    float W6 = s_w[6], W7 = s_w[7], W8 = s_w[8];
    {
        float inv = __fdividef(1.0f, ((W0+W1)+(W2+W3)) + ((W4+W5)+(W6+W7)) + W8);
        W0*=inv; W1*=inv; W2*=inv; W3*=inv; W4*=inv; W5*=inv; W6*=inv; W7*=inv; W8*=inv;
    }

    const float e0 = s_se[0], e1 = s_se[1], e2 = s_se[2];
    const float e3 = s_se[3], e4 = s_se[4], e5 = s_se[5];
    const float e6 = s_se[6], e7 = s_se[7], e8 = s_se[8];

    const bool uniform_se =
        (e0 == e1) && (e1 == e2) && (e2 == e3) && (e3 == e4) &&
        (e4 == e5) && (e5 == e6) && (e6 == e7) && (e7 == e8) && (e0 >= 0.0f);

    const int row = ty * RPT;    // top halo row of this thread's strip

    // rolling raw window rows: a = top, b = mid
    float a0 = tile[row + 0][tx], a1 = tile[row + 0][tx + 1], a2 = tile[row + 0][tx + 2];
    float b0 = tile[row + 1][tx], b1 = tile[row + 1][tx + 1], b2 = tile[row + 1][tx + 2];

    float* outp = out + (((size_t)bb * HGT) + (y0 + row)) * WID + (x0 + tx);

    if (uniform_se) {
        // sort(s*x) = s*sort(x) for uniform s>=0: fold s into weights,
        // sort raw values with first-touch fresh registers (no copies, no FMULs).
        const float s = e0;
        const float P0 = W0 * s, P7 = W7 * s, P8 = W8 * s;
        const float A1 = 0.5f*s*(W1+W2), B1 = 0.5f*s*(W2-W1);
        const float A3 = 0.5f*s*(W3+W4), B3 = 0.5f*s*(W4-W3);
        const float A5 = 0.5f*s*(W5+W6), B5 = 0.5f*s*(W6-W5);

        #pragma unroll
        for (int yy = 0; yy < RPT; yy++) {
            float c0 = tile[row + 2 + yy][tx];
            float c1 = tile[row + 2 + yy][tx + 1];
            float c2 = tile[row + 2 + yy][tx + 2];

            // layer 1 of the 25-CE network, reading sources directly:
            // pairs (0,3)(1,7)(2,5)(4,8) over v = (a0,a1,a2,b0,b1,b2,c0,c1,c2)
            float v0 = fminf(a0, b0), v3 = fmaxf(a0, b0);
            float v1 = fminf(a1, c1), v7 = fmaxf(a1, c1);
            float v2 = fminf(a2, b2), v5 = fmaxf(a2, b2);
            float v4 = fminf(b1, c2), v8 = fmaxf(b1, c2);
            // layer 2: (0,7)(2,4)(3,8)(5,6) — v6 first-touched from c0
            CE(v0, v7) CE(v2, v4) CE(v3, v8)
            float v6 = fmaxf(v5, c0); v5 = fminf(v5, c0);
            // layers 3-6
            CE(v0,v2) CE(v1,v3) CE(v4,v5) CE(v7,v8)
            CE(v1,v4) CE(v3,v6) CE(v5,v7)
            CE(v0,v1) CE(v2,v4) CE(v3,v5) CE(v6,v8)
            CE(v2,v3) CE(v4,v5) CE(v6,v7)

            // analytic final layer + softmax dot (fma pipe)
            float s1 = v1 + v2, d1 = v1 - v2;
            float s3 = v3 + v4, d3 = v3 - v4;
            float s5 = v5 + v6, d5 = v5 - v6;
            float ra = fmaf(v0, P0, fmaf(s1, A1, fabsf(d1) * B1));
            float rb = fmaf(s3, A3, fmaf(fabsf(d3), B3, s5 * A5));
            float rc = fmaf(fabsf(d5), B5, fmaf(v7, P7, v8 * P8));

            outp[(size_t)yy * WID] = (ra + rb) + rc;

            a0 = b0; a1 = b1; a2 = b2;
            b0 = c0; b1 = c1; b2 = c2;
        }
    } else {
        // general path: per-element SE weighting (doubles as the copy)
        const float P0 = W0, P7 = W7, P8 = W8;
        const float A1 = 0.5f*(W1+W2), B1 = 0.5f*(W2-W1);
        const float A3 = 0.5f*(W3+W4), B3 = 0.5f*(W4-W3);
        const float A5 = 0.5f*(W5+W6), B5 = 0.5f*(W6-W5);

        #pragma unroll
        for (int yy = 0; yy < RPT; yy++) {
            float c0 = tile[row + 2 + yy][tx];
            float c1 = tile[row + 2 + yy][tx + 1];
            float c2 = tile[row + 2 + yy][tx + 2];

            float v0 = a0 * e0, v1 = a1 * e1, v2 = a2 * e2;
            float v3 = b0 * e3, v4 = b1 * e4, v5 = b2 * e5;
            float v6 = c0 * e6, v7 = c1 * e7, v8 = c2 * e8;

            CE(v0,v3) CE(v1,v7) CE(v2,v5) CE(v4,v8)
            CE(v0,v7) CE(v2,v4) CE(v3,v8) CE(v5,v6)
            CE(v0,v2) CE(v1,v3) CE(v4,v5) CE(v7,v8)
            CE(v1,v4) CE(v3,v6) CE(v5,v7)
            CE(v0,v1) CE(v2,v4) CE(v3,v5) CE(v6,v8)
            CE(v2,v3) CE(v4,v5) CE(v6,v7)

            float s1 = v1 + v2, d1 = v1 - v2;
            float s3 = v3 + v4, d3 = v3 - v4;
            float s5 = v5 + v6, d5 = v5 - v6;
            float ra = fmaf(v0, P0, fmaf(s1, A1, fabsf(d1) * B1));
            float rb = fmaf(s3, A3, fmaf(fabsf(d3), B3, s5 * A5));
            float rc = fmaf(fabsf(d5), B5, fmaf(v7, P7, v8 * P8));

            outp[(size_t)yy * WID] = (ra + rb) + rc;

            a0 = b0; a1 = b1; a2 = b2;
            b0 = c0; b1 = c1; b2 = c2;
        }
    }
}

extern "C" void kernel_launch(void* const* d_in, const int* in_sizes, int n_in,
                              void* d_out, int out_size)
{
    const float* x   = (const float*)d_in[0];
    const float* se  = (const float*)d_in[1];
    const float* rnk = (const float*)d_in[2];
    float* out       = (float*)d_out;

    dim3 block(BX, BY);
    dim3 grid(WID / BX, HGT / (BY * RPT), 32);
    morph2d_kernel<<<grid, block>>>(x, se, rnk, out);
}